// round 9
// baseline (speedup 1.0000x reference)
#include <cuda_runtime.h>
#include <cuda_fp16.h>

#define NS   8
#define HH   128
#define WW   128
#define HWP  (HH*WW)      // 16384
#define BB   32
#define BSPL 16           // batches per temporal pass (L2 residency ~50 MB)
#define EPSV 1e-8f
#define TH   8            // rows per block in half-step kernel

typedef unsigned long long ull;

// ---------------- scratch (static device memory, no allocation) ----------------
// H0 is CHANNEL-LAST: [b][h*W+w][i*8+j]  -> 128 contiguous bytes per pixel
__device__ __half g_H0[(size_t)BB*HWP*NS*NS];   // 67 MB
__device__ __half g_r [(size_t)BB*NS*HWP];      // 8.4 MB  [b][i][h][w]
__device__ __half g_c [(size_t)BB*NS*HWP];      // 8.4 MB  [b][j][h][w]
__device__ __half g_mA[(size_t)BB*NS*HWP];      // 8.4 MB marginal ping
__device__ __half g_mB[(size_t)BB*NS*HWP];      // 8.4 MB marginal pong

// ---------------- separable gaussian weights (bandwidth 0.5, normalized) -------
constexpr double d_e2 = 0.13533528323661270231;
constexpr double d_e8 = 0.00033546262790251185;
constexpr double d_s  = 1.0 + 2.0*d_e2 + 2.0*d_e8;
#define KW0 ((float)(d_e8/d_s))
#define KW1 ((float)(d_e2/d_s))
#define KW2 ((float)(1.0 /d_s))

// ---------------- packed f32x2 helpers (sm_100+) --------------------------------
__device__ __forceinline__ ull f32x2_pack(float x, float y) {
    ull r; asm("mov.b64 %0, {%1, %2};" : "=l"(r) : "f"(x), "f"(y)); return r;
}
__device__ __forceinline__ void f32x2_unpack(ull v, float& x, float& y) {
    asm("mov.b64 {%0, %1}, %2;" : "=f"(x), "=f"(y) : "l"(v));
}
__device__ __forceinline__ ull f32x2_fma(ull a, ull b, ull c) {
    ull d; asm("fma.rn.f32x2 %0, %1, %2, %3;" : "=l"(d) : "l"(a), "l"(b), "l"(c)); return d;
}

// ================= init: H0(channel-last) = exp(log); marg0; r=c=1 ==============
// One warp handles 32 consecutive pixels of one batch; smem tile stages the
// transpose so both the plane-major reads and channel-last writes coalesce.
__global__ __launch_bounds__(256) void k_init(const float* __restrict__ lg) {
    __shared__ __half sm[8][32][72];   // [warp][pixel][ch], stride 72 -> 16B-aligned rows

    const int warp = threadIdx.x >> 5, lane = threadIdx.x & 31;
    const int gw   = blockIdx.x*8 + warp;      // 16384 warps total
    const int b    = gw >> 9;                  // 512 warps per batch
    const int pixb = (gw & 511) << 5;          // 32 pixels per warp

    const __half one = __float2half(1.0f);
    #pragma unroll
    for (int i = 0; i < NS; i++) {
        float acc = 0.f;
        #pragma unroll
        for (int j = 0; j < NS; j++) {
            float v = lg[((size_t)(b*64 + i*8 + j))*HWP + pixb + lane];
            float e = expf(v);
            acc += e;
            sm[warp][lane][i*8 + j] = __float2half(e);
        }
        size_t moff = ((size_t)(b*NS + i))*HWP + pixb + lane;
        g_mA[moff] = __float2half(acc);
        g_r[moff]  = one;
        g_c[moff]  = one;
    }
    __syncwarp();

    const size_t obase = ((size_t)b*HWP + pixb + lane)*64;
    #pragma unroll
    for (int k = 0; k < 8; k++)
        *(uint4*)(g_H0 + obase + k*8) = *(const uint4*)(&sm[warp][lane][k*8]);
}

// ================= fused half step (2 px/thread, 512 threads) ===================
// MODE 0: smooth marg_in -> r /= (s+eps); marg_out_j = c_j * sum_i H0[i][j]*r_i
// MODE 1: smooth marg_in -> c /= (s+eps); marg_out_i = r_i * sum_j H0[i][j]*c_j
template<int MODE>
__global__ __launch_bounds__(512, 2) void k_half(int ping, int b0) {
    __shared__ __align__(16) __half sm_m[TH+4][NS][WW];  // marginal tile + halo (24 KB)
    __shared__ __align__(16) float  sm_t[TH  ][NS][WW];  // vertical conv result (32 KB)

    const __half* __restrict__ min_ = ping ? g_mB : g_mA;
    __half*       __restrict__ mout = ping ? g_mA : g_mB;
    __half*       upd = (MODE == 0) ? g_r : g_c;
    const __half* oth = (MODE == 0) ? g_c : g_r;

    const int b   = b0 + blockIdx.y;
    const int h0  = blockIdx.x * TH;
    const int tid = threadIdx.x;

    // ---- stage 1: load marginal tile (rows h0-2 .. h0+TH+1, circular) ----------
    #pragma unroll
    for (int k = 0; k < 3; k++) {               // 1536 uint4 / 512 threads
        int idx = tid + k*512;
        int rr  = idx >> 7;
        int rem = idx & 127;
        int ch  = rem >> 4;
        int w8  = (rem & 15) << 3;
        int gh  = (h0 - 2 + rr) & (HH-1);
        *(uint4*)(&sm_m[rr][ch][w8]) =
            *(const uint4*)(min_ + ((size_t)(b*NS + ch))*HWP + gh*WW + w8);
    }
    __syncthreads();

    // ---- stage 2: vertical 5-tap, half2 granularity ----------------------------
    #pragma unroll
    for (int k = 0; k < 8; k++) {
        int e2 = tid + k*512;
        int r  = e2 >> 9;
        int ch = (e2 >> 6) & 7;
        int w2 = (e2 & 63) << 1;
        float2 a0 = __half22float2(*(const __half2*)(&sm_m[r  ][ch][w2]));
        float2 a1 = __half22float2(*(const __half2*)(&sm_m[r+1][ch][w2]));
        float2 a2 = __half22float2(*(const __half2*)(&sm_m[r+2][ch][w2]));
        float2 a3 = __half22float2(*(const __half2*)(&sm_m[r+3][ch][w2]));
        float2 a4 = __half22float2(*(const __half2*)(&sm_m[r+4][ch][w2]));
        float2 o;
        o.x = KW0*a0.x + KW1*a1.x + KW2*a2.x + KW1*a3.x + KW0*a4.x;
        o.y = KW0*a0.y + KW1*a1.y + KW2*a2.y + KW1*a3.y + KW0*a4.y;
        *(float2*)(&sm_t[r][ch][w2]) = o;
    }
    __syncthreads();

    // ---- stage 3: horizontal 5-tap, factor update, contraction (2 px/thread) ---
    const int row = tid >> 6;                   // 0..7
    const int w0  = (tid & 63) << 1;            // 0,2,..,126
    const int h   = h0 + row;
    const size_t pixoff = (size_t)h*WW + w0;

    float un0[NS], un1[NS];
    #pragma unroll
    for (int u = 0; u < NS; u++) {
        float tm2 = sm_t[row][u][(w0 + 126) & 127];
        float tm1 = sm_t[row][u][(w0 + 127) & 127];
        float t0  = sm_t[row][u][w0];
        float t1  = sm_t[row][u][w0 + 1];
        float tp2 = sm_t[row][u][(w0 + 2) & 127];
        float tp3 = sm_t[row][u][(w0 + 3) & 127];
        float s0 = KW0*tm2 + KW1*tm1 + KW2*t0 + KW1*t1 + KW0*tp2;
        float s1 = KW0*tm1 + KW1*t0  + KW2*t1 + KW1*tp2 + KW0*tp3;

        size_t off = ((size_t)(b*NS + u))*HWP + pixoff;
        float2 f = __half22float2(*(const __half2*)(upd + off));
        un0[u] = __fdividef(f.x, s0 + EPSV);
        un1[u] = __fdividef(f.y, s1 + EPSV);
        *(__half2*)(upd + off) = __floats2half2_rn(un0[u], un1[u]);
    }

    // ---- contraction on channel-last H0: 8 uint4 per pixel ---------------------
    const __half* cl = g_H0 + ((size_t)b*HWP + pixoff)*64;
    float res0[NS], res1[NS];

    #pragma unroll
    for (int px = 0; px < 2; px++) {
        const uint4* hp  = (const uint4*)(cl + px*64);
        const float* unp = px ? un1 : un0;
        float*       res = px ? res1 : res0;

        if (MODE == 0) {
            // output per j: acc_jpair += H[u][j-pair] * un[u] (broadcast)
            ull a0 = 0, a1 = 0, a2 = 0, a3 = 0;
            #pragma unroll
            for (int u = 0; u < NS; u++) {
                uint4 q = hp[u];
                ull ub = f32x2_pack(unp[u], unp[u]);
                float2 h0_ = __half22float2(*(__half2*)&q.x);
                float2 h1_ = __half22float2(*(__half2*)&q.y);
                float2 h2_ = __half22float2(*(__half2*)&q.z);
                float2 h3_ = __half22float2(*(__half2*)&q.w);
                a0 = f32x2_fma(f32x2_pack(h0_.x, h0_.y), ub, a0);
                a1 = f32x2_fma(f32x2_pack(h1_.x, h1_.y), ub, a1);
                a2 = f32x2_fma(f32x2_pack(h2_.x, h2_.y), ub, a2);
                a3 = f32x2_fma(f32x2_pack(h3_.x, h3_.y), ub, a3);
            }
            f32x2_unpack(a0, res[0], res[1]);
            f32x2_unpack(a1, res[2], res[3]);
            f32x2_unpack(a2, res[4], res[5]);
            f32x2_unpack(a3, res[6], res[7]);
        } else {
            // output per i: res_i = dot(H[i][:], un[:])
            ull up0 = f32x2_pack(unp[0], unp[1]);
            ull up1 = f32x2_pack(unp[2], unp[3]);
            ull up2 = f32x2_pack(unp[4], unp[5]);
            ull up3 = f32x2_pack(unp[6], unp[7]);
            #pragma unroll
            for (int i = 0; i < NS; i++) {
                uint4 q = hp[i];
                float2 h0_ = __half22float2(*(__half2*)&q.x);
                float2 h1_ = __half22float2(*(__half2*)&q.y);
                float2 h2_ = __half22float2(*(__half2*)&q.z);
                float2 h3_ = __half22float2(*(__half2*)&q.w);
                ull r2 = f32x2_fma(f32x2_pack(h0_.x, h0_.y), up0, 0ull);
                r2 = f32x2_fma(f32x2_pack(h1_.x, h1_.y), up1, r2);
                r2 = f32x2_fma(f32x2_pack(h2_.x, h2_.y), up2, r2);
                r2 = f32x2_fma(f32x2_pack(h3_.x, h3_.y), up3, r2);
                float x, y; f32x2_unpack(r2, x, y);
                res[i] = x + y;
            }
        }
    }

    #pragma unroll
    for (int v = 0; v < NS; v++) {
        size_t off = ((size_t)(b*NS + v))*HWP + pixoff;
        float2 o = __half22float2(*(const __half2*)(oth + off));
        *(__half2*)(mout + off) = __floats2half2_rn(res0[v]*o.x, res1[v]*o.y);
    }
}

// ================= final: out = exp(log)*r_i*c_j + eps (fp32 path) =============
__global__ void k_final(const float* __restrict__ lg, float* __restrict__ out) {
    int t   = blockIdx.x*blockDim.x + threadIdx.x;
    int b   = t >> 12;
    int pix = (t & 4095) << 2;

    float cf[NS][4];
    #pragma unroll
    for (int j = 0; j < NS; j++) {
        uint2 cv = *(const uint2*)(g_c + ((size_t)(b*NS + j))*HWP + pix);
        float2 c01 = __half22float2(*(__half2*)&cv.x);
        float2 c23 = __half22float2(*(__half2*)&cv.y);
        cf[j][0] = c01.x; cf[j][1] = c01.y; cf[j][2] = c23.x; cf[j][3] = c23.y;
    }
    #pragma unroll
    for (int i = 0; i < NS; i++) {
        uint2 rw = *(const uint2*)(g_r + ((size_t)(b*NS + i))*HWP + pix);
        float2 r01 = __half22float2(*(__half2*)&rw.x);
        float2 r23 = __half22float2(*(__half2*)&rw.y);
        #pragma unroll
        for (int j = 0; j < NS; j++) {
            size_t off = ((size_t)(b*NS*NS + i*NS + j))*HWP + pix;
            float4 v = *(const float4*)(lg + off);
            float4 o;
            o.x = expf(v.x)*r01.x*cf[j][0] + EPSV;
            o.y = expf(v.y)*r01.y*cf[j][1] + EPSV;
            o.z = expf(v.z)*r23.x*cf[j][2] + EPSV;
            o.w = expf(v.w)*r23.y*cf[j][3] + EPSV;
            *(float4*)(out + off) = o;
        }
    }
}

// ================= launch =======================================================
extern "C" void kernel_launch(void* const* d_in, const int* in_sizes, int n_in,
                              void* d_out, int out_size) {
    (void)in_sizes; (void)n_in; (void)out_size;
    const float* lg  = (const float*)d_in[0];
    float*       out = (float*)d_out;

    k_init<<<2048, 256>>>(lg);

    dim3 hg(HH/TH, BSPL);            // (16,16) = 256 blocks x 512 thr = one wave
    for (int pass = 0; pass < BB/BSPL; pass++) {
        int b0 = pass * BSPL;        // temporal blocking: slice stays in L2
        for (int it = 0; it < 20; it++) {
            k_half<0><<<hg, 512>>>(0, b0);   // row step: update r
            k_half<1><<<hg, 512>>>(1, b0);   // col step: update c
        }
    }

    k_final<<<512, 256>>>(lg, out);
}

// round 11
// speedup vs baseline: 1.8347x; 1.8347x over previous
#include <cuda_runtime.h>
#include <cuda_fp16.h>

#define NS   8
#define HH   128
#define WW   128
#define HWP  (HH*WW)      // 16384
#define BB   32
#define BSPL 16           // batches per temporal pass (L2 residency ~50 MB)
#define EPSV 1e-8f
#define TH   4            // rows per block in half-step kernel

// ---------------- scratch (static device memory, no allocation) ----------------
// H0 plane-major [b][i*8+j][h][w]  -> warp-coalesced LDG.32 per channel
__device__ __half g_H0[(size_t)BB*NS*NS*HWP];   // 67 MB
__device__ __half g_r [(size_t)BB*NS*HWP];      // 8.4 MB  [b][i][h][w]
__device__ __half g_c [(size_t)BB*NS*HWP];      // 8.4 MB  [b][j][h][w]
__device__ __half g_mA[(size_t)BB*NS*HWP];      // 8.4 MB marginal ping
__device__ __half g_mB[(size_t)BB*NS*HWP];      // 8.4 MB marginal pong

// ---------------- separable gaussian weights (bandwidth 0.5, normalized) -------
constexpr double d_e2 = 0.13533528323661270231;
constexpr double d_e8 = 0.00033546262790251185;
constexpr double d_s  = 1.0 + 2.0*d_e2 + 2.0*d_e8;
#define KW0 ((float)(d_e8/d_s))
#define KW1 ((float)(d_e2/d_s))
#define KW2 ((float)(1.0 /d_s))

// ================= init: H0 = exp(log), marg0 = sum_j H0, r=c=1 ================
__global__ void k_init(const float* __restrict__ lg) {
    int t   = blockIdx.x*blockDim.x + threadIdx.x;   // 131072 threads
    int b   = t >> 12;
    int pix = (t & 4095) << 2;

    const __half2 one2 = __floats2half2_rn(1.f, 1.f);
    #pragma unroll
    for (int i = 0; i < NS; i++) {
        float a0 = 0.f, a1 = 0.f, a2 = 0.f, a3 = 0.f;
        #pragma unroll
        for (int j = 0; j < NS; j++) {
            size_t off = ((size_t)(b*NS*NS + i*NS + j))*HWP + pix;
            float4 v = *(const float4*)(lg + off);
            float e0 = expf(v.x), e1 = expf(v.y), e2 = expf(v.z), e3 = expf(v.w);
            __half2* hp = (__half2*)(g_H0 + off);
            hp[0] = __floats2half2_rn(e0, e1);
            hp[1] = __floats2half2_rn(e2, e3);
            a0 += e0; a1 += e1; a2 += e2; a3 += e3;
        }
        size_t moff = ((size_t)(b*NS + i))*HWP + pix;
        __half2* mp = (__half2*)(g_mA + moff);
        mp[0] = __floats2half2_rn(a0, a1);
        mp[1] = __floats2half2_rn(a2, a3);
        ((__half2*)(g_r + moff))[0] = one2;
        ((__half2*)(g_r + moff))[1] = one2;
        ((__half2*)(g_c + moff))[0] = one2;
        ((__half2*)(g_c + moff))[1] = one2;
    }
}

// ================= fused half step (2 px/thread, 256 threads, occ 4) ============
// MODE 0: smooth marg_in -> r /= (s+eps); marg_out_j = c_j * sum_i H0[i][j]*r_i
// MODE 1: smooth marg_in -> c /= (s+eps); marg_out_i = r_i * sum_j H0[i][j]*c_j
template<int MODE>
__global__ __launch_bounds__(256, 4) void k_half(int ping, int b0) {
    __shared__ __align__(16) __half sm_m[TH+4][NS][WW];  // marginal tile + halo (16 KB)
    __shared__ __align__(16) float  sm_t[TH  ][NS][WW];  // vertical conv result (16 KB)

    const __half* __restrict__ min_ = ping ? g_mB : g_mA;
    __half*       __restrict__ mout = ping ? g_mA : g_mB;
    __half*       upd = (MODE == 0) ? g_r : g_c;
    const __half* oth = (MODE == 0) ? g_c : g_r;

    const int b   = b0 + blockIdx.y;
    const int h0  = blockIdx.x * TH;
    const int tid = threadIdx.x;

    // ---- stage 1: load marginal tile (rows h0-2 .. h0+TH+1, circular) ----------
    #pragma unroll
    for (int k = 0; k < 4; k++) {               // 1024 uint4 / 256 threads
        int idx = tid + k*256;
        int rr  = idx >> 7;                     // 0..7
        int rem = idx & 127;
        int ch  = rem >> 4;
        int w8  = (rem & 15) << 3;
        int gh  = (h0 - 2 + rr) & (HH-1);
        *(uint4*)(&sm_m[rr][ch][w8]) =
            *(const uint4*)(min_ + ((size_t)(b*NS + ch))*HWP + gh*WW + w8);
    }
    __syncthreads();

    // ---- stage 2: vertical 5-tap, half2 granularity (2048 units / 256 thr) -----
    #pragma unroll
    for (int k = 0; k < 8; k++) {
        int e2 = tid + k*256;
        int r  = e2 >> 9;                       // 0..3
        int ch = (e2 >> 6) & 7;
        int w2 = (e2 & 63) << 1;
        float2 a0 = __half22float2(*(const __half2*)(&sm_m[r  ][ch][w2]));
        float2 a1 = __half22float2(*(const __half2*)(&sm_m[r+1][ch][w2]));
        float2 a2 = __half22float2(*(const __half2*)(&sm_m[r+2][ch][w2]));
        float2 a3 = __half22float2(*(const __half2*)(&sm_m[r+3][ch][w2]));
        float2 a4 = __half22float2(*(const __half2*)(&sm_m[r+4][ch][w2]));
        float2 o;
        o.x = KW0*a0.x + KW1*a1.x + KW2*a2.x + KW1*a3.x + KW0*a4.x;
        o.y = KW0*a0.y + KW1*a1.y + KW2*a2.y + KW1*a3.y + KW0*a4.y;
        *(float2*)(&sm_t[r][ch][w2]) = o;
    }
    __syncthreads();

    // ---- stage 3: horizontal 5-tap, factor update, contraction (2 px/thread) ---
    const int row = tid >> 6;                   // 0..3
    const int w0  = (tid & 63) << 1;            // 0,2,..,126
    const int h   = h0 + row;
    const size_t pixoff = (size_t)h*WW + w0;
    const size_t hbase  = (size_t)b*NS*NS*HWP + pixoff;

    float un[NS][2];
    #pragma unroll
    for (int u = 0; u < NS; u++) {
        float tm2 = sm_t[row][u][(w0 + 126) & 127];
        float tm1 = sm_t[row][u][(w0 + 127) & 127];
        float t0  = sm_t[row][u][w0];
        float t1  = sm_t[row][u][w0 + 1];
        float tp2 = sm_t[row][u][(w0 + 2) & 127];
        float tp3 = sm_t[row][u][(w0 + 3) & 127];
        float s0 = KW0*tm2 + KW1*tm1 + KW2*t0 + KW1*t1 + KW0*tp2;
        float s1 = KW0*tm1 + KW1*t0  + KW2*t1 + KW1*tp2 + KW0*tp3;

        size_t off = ((size_t)(b*NS + u))*HWP + pixoff;
        float2 f = __half22float2(*(const __half2*)(upd + off));
        un[u][0] = __fdividef(f.x, s0 + EPSV);
        un[u][1] = __fdividef(f.y, s1 + EPSV);
        *(__half2*)(upd + off) = __floats2half2_rn(un[u][0], un[u][1]);
    }

    #pragma unroll
    for (int vh = 0; vh < 2; vh++) {
        float acc[4][2];
        #pragma unroll
        for (int v = 0; v < 4; v++) acc[v][0] = acc[v][1] = 0.f;

        #pragma unroll
        for (int u = 0; u < NS; u++) {
            #pragma unroll
            for (int v = 0; v < 4; v++) {
                int vv = vh*4 + v;
                int cc = (MODE == 0) ? (u*NS + vv) : (vv*NS + u);
                float2 f = __half22float2(*(const __half2*)(g_H0 + hbase + (size_t)cc*HWP));
                acc[v][0] += f.x * un[u][0];
                acc[v][1] += f.y * un[u][1];
            }
        }

        #pragma unroll
        for (int v = 0; v < 4; v++) {
            int vv = vh*4 + v;
            size_t off = ((size_t)(b*NS + vv))*HWP + pixoff;
            float2 o = __half22float2(*(const __half2*)(oth + off));
            *(__half2*)(mout + off) = __floats2half2_rn(acc[v][0]*o.x, acc[v][1]*o.y);
        }
    }
}

// ================= final: out = exp(log)*r_i*c_j + eps (fp32 path) =============
__global__ void k_final(const float* __restrict__ lg, float* __restrict__ out) {
    int t   = blockIdx.x*blockDim.x + threadIdx.x;
    int b   = t >> 12;
    int pix = (t & 4095) << 2;

    float cf[NS][4];
    #pragma unroll
    for (int j = 0; j < NS; j++) {
        uint2 cv = *(const uint2*)(g_c + ((size_t)(b*NS + j))*HWP + pix);
        float2 c01 = __half22float2(*(__half2*)&cv.x);
        float2 c23 = __half22float2(*(__half2*)&cv.y);
        cf[j][0] = c01.x; cf[j][1] = c01.y; cf[j][2] = c23.x; cf[j][3] = c23.y;
    }
    #pragma unroll
    for (int i = 0; i < NS; i++) {
        uint2 rw = *(const uint2*)(g_r + ((size_t)(b*NS + i))*HWP + pix);
        float2 r01 = __half22float2(*(__half2*)&rw.x);
        float2 r23 = __half22float2(*(__half2*)&rw.y);
        #pragma unroll
        for (int j = 0; j < NS; j++) {
            size_t off = ((size_t)(b*NS*NS + i*NS + j))*HWP + pix;
            float4 v = *(const float4*)(lg + off);
            float4 o;
            o.x = expf(v.x)*r01.x*cf[j][0] + EPSV;
            o.y = expf(v.y)*r01.y*cf[j][1] + EPSV;
            o.z = expf(v.z)*r23.x*cf[j][2] + EPSV;
            o.w = expf(v.w)*r23.y*cf[j][3] + EPSV;
            *(float4*)(out + off) = o;
        }
    }
}

// ================= launch =======================================================
extern "C" void kernel_launch(void* const* d_in, const int* in_sizes, int n_in,
                              void* d_out, int out_size) {
    (void)in_sizes; (void)n_in; (void)out_size;
    const float* lg  = (const float*)d_in[0];
    float*       out = (float*)d_out;

    k_init<<<512, 256>>>(lg);

    dim3 hg(HH/TH, BSPL);            // (32,16) = 512 blocks x 256 thr, occ 4 = one wave
    for (int pass = 0; pass < BB/BSPL; pass++) {
        int b0 = pass * BSPL;        // temporal blocking: slice stays in L2
        for (int it = 0; it < 20; it++) {
            k_half<0><<<hg, 256>>>(0, b0);   // row step: update r
            k_half<1><<<hg, 256>>>(1, b0);   // col step: update c
        }
    }

    k_final<<<512, 256>>>(lg, out);
}

// round 12
// speedup vs baseline: 1.9578x; 1.0671x over previous
#include <cuda_runtime.h>
#include <cuda_fp16.h>

#define NS   8
#define HH   128
#define WW   128
#define HWP  (HH*WW)      // 16384
#define BB   32
#define BSPL 16           // batches per chain (two chains overlap; both fit L2)
#define EPSV 1e-8f
#define TH   4            // rows per block in half-step kernel

// ---------------- scratch (static device memory, no allocation) ----------------
// H0 plane-major [b][i*8+j][h][w]  -> warp-coalesced LDG.32 per channel
__device__ __half g_H0[(size_t)BB*NS*NS*HWP];   // 67 MB
__device__ __half g_r [(size_t)BB*NS*HWP];      // 8.4 MB  [b][i][h][w]
__device__ __half g_c [(size_t)BB*NS*HWP];      // 8.4 MB  [b][j][h][w]
__device__ __half g_mA[(size_t)BB*NS*HWP];      // 8.4 MB marginal ping
__device__ __half g_mB[(size_t)BB*NS*HWP];      // 8.4 MB marginal pong

// ---------------- separable gaussian weights (bandwidth 0.5, normalized) -------
constexpr double d_e2 = 0.13533528323661270231;
constexpr double d_e8 = 0.00033546262790251185;
constexpr double d_s  = 1.0 + 2.0*d_e2 + 2.0*d_e8;
#define KW0 ((float)(d_e8/d_s))
#define KW1 ((float)(d_e2/d_s))
#define KW2 ((float)(1.0 /d_s))

// ================= init: H0 = exp(log), marg0 = sum_j H0, r=c=1 ================
__global__ void k_init(const float* __restrict__ lg) {
    int t   = blockIdx.x*blockDim.x + threadIdx.x;   // 131072 threads
    int b   = t >> 12;
    int pix = (t & 4095) << 2;

    const __half2 one2 = __floats2half2_rn(1.f, 1.f);
    #pragma unroll
    for (int i = 0; i < NS; i++) {
        float a0 = 0.f, a1 = 0.f, a2 = 0.f, a3 = 0.f;
        #pragma unroll
        for (int j = 0; j < NS; j++) {
            size_t off = ((size_t)(b*NS*NS + i*NS + j))*HWP + pix;
            float4 v = *(const float4*)(lg + off);
            float e0 = expf(v.x), e1 = expf(v.y), e2 = expf(v.z), e3 = expf(v.w);
            __half2* hp = (__half2*)(g_H0 + off);
            hp[0] = __floats2half2_rn(e0, e1);
            hp[1] = __floats2half2_rn(e2, e3);
            a0 += e0; a1 += e1; a2 += e2; a3 += e3;
        }
        size_t moff = ((size_t)(b*NS + i))*HWP + pix;
        __half2* mp = (__half2*)(g_mA + moff);
        mp[0] = __floats2half2_rn(a0, a1);
        mp[1] = __floats2half2_rn(a2, a3);
        ((__half2*)(g_r + moff))[0] = one2;
        ((__half2*)(g_r + moff))[1] = one2;
        ((__half2*)(g_c + moff))[0] = one2;
        ((__half2*)(g_c + moff))[1] = one2;
    }
}

// ================= fused half step (2 px/thread, 256 threads, occ 4) ============
// MODE 0: smooth marg_in -> r /= (s+eps); marg_out_j = c_j * sum_i H0[i][j]*r_i
// MODE 1: smooth marg_in -> c /= (s+eps); marg_out_i = r_i * sum_j H0[i][j]*c_j
template<int MODE>
__global__ __launch_bounds__(256, 4) void k_half(int ping, int b0) {
    __shared__ __align__(16) __half sm_m[TH+4][NS][WW];  // marginal tile + halo (16 KB)
    __shared__ __align__(16) float  sm_t[TH  ][NS][WW];  // vertical conv result (16 KB)

    const __half* __restrict__ min_ = ping ? g_mB : g_mA;
    __half*       __restrict__ mout = ping ? g_mA : g_mB;
    __half*       upd = (MODE == 0) ? g_r : g_c;
    const __half* oth = (MODE == 0) ? g_c : g_r;

    const int b   = b0 + blockIdx.y;
    const int h0  = blockIdx.x * TH;
    const int tid = threadIdx.x;

    // ---- stage 1: load marginal tile (rows h0-2 .. h0+TH+1, circular) ----------
    #pragma unroll
    for (int k = 0; k < 4; k++) {               // 1024 uint4 / 256 threads
        int idx = tid + k*256;
        int rr  = idx >> 7;                     // 0..7
        int rem = idx & 127;
        int ch  = rem >> 4;
        int w8  = (rem & 15) << 3;
        int gh  = (h0 - 2 + rr) & (HH-1);
        *(uint4*)(&sm_m[rr][ch][w8]) =
            *(const uint4*)(min_ + ((size_t)(b*NS + ch))*HWP + gh*WW + w8);
    }
    __syncthreads();

    // ---- stage 2: vertical 5-tap, half2 granularity (2048 units / 256 thr) -----
    #pragma unroll
    for (int k = 0; k < 8; k++) {
        int e2 = tid + k*256;
        int r  = e2 >> 9;                       // 0..3
        int ch = (e2 >> 6) & 7;
        int w2 = (e2 & 63) << 1;
        float2 a0 = __half22float2(*(const __half2*)(&sm_m[r  ][ch][w2]));
        float2 a1 = __half22float2(*(const __half2*)(&sm_m[r+1][ch][w2]));
        float2 a2 = __half22float2(*(const __half2*)(&sm_m[r+2][ch][w2]));
        float2 a3 = __half22float2(*(const __half2*)(&sm_m[r+3][ch][w2]));
        float2 a4 = __half22float2(*(const __half2*)(&sm_m[r+4][ch][w2]));
        float2 o;
        o.x = KW0*a0.x + KW1*a1.x + KW2*a2.x + KW1*a3.x + KW0*a4.x;
        o.y = KW0*a0.y + KW1*a1.y + KW2*a2.y + KW1*a3.y + KW0*a4.y;
        *(float2*)(&sm_t[r][ch][w2]) = o;
    }
    __syncthreads();

    // ---- stage 3: horizontal 5-tap, factor update, contraction (2 px/thread) ---
    const int row = tid >> 6;                   // 0..3
    const int w0  = (tid & 63) << 1;            // 0,2,..,126
    const int h   = h0 + row;
    const size_t pixoff = (size_t)h*WW + w0;
    const size_t hbase  = (size_t)b*NS*NS*HWP + pixoff;

    float un[NS][2];
    #pragma unroll
    for (int u = 0; u < NS; u++) {
        float tm2 = sm_t[row][u][(w0 + 126) & 127];
        float tm1 = sm_t[row][u][(w0 + 127) & 127];
        float t0  = sm_t[row][u][w0];
        float t1  = sm_t[row][u][w0 + 1];
        float tp2 = sm_t[row][u][(w0 + 2) & 127];
        float tp3 = sm_t[row][u][(w0 + 3) & 127];
        float s0 = KW0*tm2 + KW1*tm1 + KW2*t0 + KW1*t1 + KW0*tp2;
        float s1 = KW0*tm1 + KW1*t0  + KW2*t1 + KW1*tp2 + KW0*tp3;

        size_t off = ((size_t)(b*NS + u))*HWP + pixoff;
        float2 f = __half22float2(*(const __half2*)(upd + off));
        un[u][0] = __fdividef(f.x, s0 + EPSV);
        un[u][1] = __fdividef(f.y, s1 + EPSV);
        *(__half2*)(upd + off) = __floats2half2_rn(un[u][0], un[u][1]);
    }

    #pragma unroll
    for (int vh = 0; vh < 2; vh++) {
        float acc[4][2];
        #pragma unroll
        for (int v = 0; v < 4; v++) acc[v][0] = acc[v][1] = 0.f;

        #pragma unroll
        for (int u = 0; u < NS; u++) {
            #pragma unroll
            for (int v = 0; v < 4; v++) {
                int vv = vh*4 + v;
                int cc = (MODE == 0) ? (u*NS + vv) : (vv*NS + u);
                float2 f = __half22float2(*(const __half2*)(g_H0 + hbase + (size_t)cc*HWP));
                acc[v][0] += f.x * un[u][0];
                acc[v][1] += f.y * un[u][1];
            }
        }

        #pragma unroll
        for (int v = 0; v < 4; v++) {
            int vv = vh*4 + v;
            size_t off = ((size_t)(b*NS + vv))*HWP + pixoff;
            float2 o = __half22float2(*(const __half2*)(oth + off));
            *(__half2*)(mout + off) = __floats2half2_rn(acc[v][0]*o.x, acc[v][1]*o.y);
        }
    }
}

// ================= final: out = exp(log)*r_i*c_j + eps (fp32 path) =============
__global__ void k_final(const float* __restrict__ lg, float* __restrict__ out) {
    int t   = blockIdx.x*blockDim.x + threadIdx.x;
    int b   = t >> 12;
    int pix = (t & 4095) << 2;

    float cf[NS][4];
    #pragma unroll
    for (int j = 0; j < NS; j++) {
        uint2 cv = *(const uint2*)(g_c + ((size_t)(b*NS + j))*HWP + pix);
        float2 c01 = __half22float2(*(__half2*)&cv.x);
        float2 c23 = __half22float2(*(__half2*)&cv.y);
        cf[j][0] = c01.x; cf[j][1] = c01.y; cf[j][2] = c23.x; cf[j][3] = c23.y;
    }
    #pragma unroll
    for (int i = 0; i < NS; i++) {
        uint2 rw = *(const uint2*)(g_r + ((size_t)(b*NS + i))*HWP + pix);
        float2 r01 = __half22float2(*(__half2*)&rw.x);
        float2 r23 = __half22float2(*(__half2*)&rw.y);
        #pragma unroll
        for (int j = 0; j < NS; j++) {
            size_t off = ((size_t)(b*NS*NS + i*NS + j))*HWP + pix;
            float4 v = *(const float4*)(lg + off);
            float4 o;
            o.x = expf(v.x)*r01.x*cf[j][0] + EPSV;
            o.y = expf(v.y)*r01.y*cf[j][1] + EPSV;
            o.z = expf(v.z)*r23.x*cf[j][2] + EPSV;
            o.w = expf(v.w)*r23.y*cf[j][3] + EPSV;
            *(float4*)(out + off) = o;
        }
    }
}

// ================= launch: two overlapped slice-chains via stream fork ==========
extern "C" void kernel_launch(void* const* d_in, const int* in_sizes, int n_in,
                              void* d_out, int out_size) {
    (void)in_sizes; (void)n_in; (void)out_size;
    const float* lg  = (const float*)d_in[0];
    float*       out = (float*)d_out;

    // one-time resources (created on the first, non-capturing correctness call;
    // reused unchanged on every call -> identical work each time)
    static cudaStream_t s2 = nullptr;
    static cudaEvent_t  evFork = nullptr, evJoin = nullptr;
    if (s2 == nullptr) {
        cudaStreamCreateWithFlags(&s2, cudaStreamNonBlocking);
        cudaEventCreateWithFlags(&evFork, cudaEventDisableTiming);
        cudaEventCreateWithFlags(&evJoin, cudaEventDisableTiming);
    }

    k_init<<<512, 256>>>(lg);

    // fork: chain B (batches 16..31) runs on s2, chain A (0..15) on legacy stream
    cudaEventRecord(evFork, 0);
    cudaStreamWaitEvent(s2, evFork, 0);

    dim3 hg(HH/TH, BSPL);            // (32,16) = 512 blocks x 256 thr per chain
    for (int it = 0; it < 20; it++) {
        k_half<0><<<hg, 256>>>(0, 0);          // chain A row step
        k_half<1><<<hg, 256>>>(1, 0);          // chain A col step
    }
    for (int it = 0; it < 20; it++) {
        k_half<0><<<hg, 256, 0, s2>>>(0, BSPL);  // chain B row step
        k_half<1><<<hg, 256, 0, s2>>>(1, BSPL);  // chain B col step
    }

    // join: final kernel needs both chains' r and c
    cudaEventRecord(evJoin, s2);
    cudaStreamWaitEvent(0, evJoin, 0);

    k_final<<<512, 256>>>(lg, out);
}

// round 13
// speedup vs baseline: 2.0952x; 1.0702x over previous
#include <cuda_runtime.h>
#include <cuda_fp16.h>

#define NS     8
#define HH     128
#define WW     128
#define HWP    (HH*WW)      // 16384
#define BB     32
#define CHAINS 4
#define CBAT   (BB/CHAINS)  // 8 batches per chain
#define EPSV   1e-8f
#define TH     4            // rows per block in half-step kernel

// ---------------- scratch (static device memory, no allocation) ----------------
// H0 plane-major [b][i*8+j][h][w]  -> warp-coalesced LDG.32 per channel
__device__ __half g_H0[(size_t)BB*NS*NS*HWP];   // 67 MB
__device__ __half g_r [(size_t)BB*NS*HWP];      // 8.4 MB  [b][i][h][w]
__device__ __half g_c [(size_t)BB*NS*HWP];      // 8.4 MB  [b][j][h][w]
__device__ __half g_mA[(size_t)BB*NS*HWP];      // 8.4 MB marginal ping
__device__ __half g_mB[(size_t)BB*NS*HWP];      // 8.4 MB marginal pong

// ---------------- separable gaussian weights (bandwidth 0.5, normalized) -------
constexpr double d_e2 = 0.13533528323661270231;
constexpr double d_e8 = 0.00033546262790251185;
constexpr double d_s  = 1.0 + 2.0*d_e2 + 2.0*d_e8;
#define KW0 ((float)(d_e8/d_s))
#define KW1 ((float)(d_e2/d_s))
#define KW2 ((float)(1.0 /d_s))

// ================= per-chain init: H0 = exp(log), marg0, r=c=1 =================
__global__ void k_init_c(const float* __restrict__ lg, int b0) {
    int t   = blockIdx.x*blockDim.x + threadIdx.x;   // 32768 threads (8 batches)
    int b   = b0 + (t >> 12);
    int pix = (t & 4095) << 2;

    const __half2 one2 = __floats2half2_rn(1.f, 1.f);
    #pragma unroll
    for (int i = 0; i < NS; i++) {
        float a0 = 0.f, a1 = 0.f, a2 = 0.f, a3 = 0.f;
        #pragma unroll
        for (int j = 0; j < NS; j++) {
            size_t off = ((size_t)(b*NS*NS + i*NS + j))*HWP + pix;
            float4 v = *(const float4*)(lg + off);
            float e0 = expf(v.x), e1 = expf(v.y), e2 = expf(v.z), e3 = expf(v.w);
            __half2* hp = (__half2*)(g_H0 + off);
            hp[0] = __floats2half2_rn(e0, e1);
            hp[1] = __floats2half2_rn(e2, e3);
            a0 += e0; a1 += e1; a2 += e2; a3 += e3;
        }
        size_t moff = ((size_t)(b*NS + i))*HWP + pix;
        __half2* mp = (__half2*)(g_mA + moff);
        mp[0] = __floats2half2_rn(a0, a1);
        mp[1] = __floats2half2_rn(a2, a3);
        ((__half2*)(g_r + moff))[0] = one2;
        ((__half2*)(g_r + moff))[1] = one2;
        ((__half2*)(g_c + moff))[0] = one2;
        ((__half2*)(g_c + moff))[1] = one2;
    }
}

// ================= fused half step (2 px/thread, 256 threads, occ 4) ============
// MODE 0: smooth marg_in -> r /= (s+eps); marg_out_j = c_j * sum_i H0[i][j]*r_i
// MODE 1: smooth marg_in -> c /= (s+eps); marg_out_i = r_i * sum_j H0[i][j]*c_j
template<int MODE>
__global__ __launch_bounds__(256, 4) void k_half(int ping, int b0) {
    __shared__ __align__(16) __half sm_m[TH+4][NS][WW];  // marginal tile + halo (16 KB)
    __shared__ __align__(16) float  sm_t[TH  ][NS][WW];  // vertical conv result (16 KB)

    const __half* __restrict__ min_ = ping ? g_mB : g_mA;
    __half*       __restrict__ mout = ping ? g_mA : g_mB;
    __half*       upd = (MODE == 0) ? g_r : g_c;
    const __half* oth = (MODE == 0) ? g_c : g_r;

    const int b   = b0 + blockIdx.y;
    const int h0  = blockIdx.x * TH;
    const int tid = threadIdx.x;

    // ---- stage 1: load marginal tile (rows h0-2 .. h0+TH+1, circular) ----------
    #pragma unroll
    for (int k = 0; k < 4; k++) {               // 1024 uint4 / 256 threads
        int idx = tid + k*256;
        int rr  = idx >> 7;                     // 0..7
        int rem = idx & 127;
        int ch  = rem >> 4;
        int w8  = (rem & 15) << 3;
        int gh  = (h0 - 2 + rr) & (HH-1);
        *(uint4*)(&sm_m[rr][ch][w8]) =
            *(const uint4*)(min_ + ((size_t)(b*NS + ch))*HWP + gh*WW + w8);
    }
    __syncthreads();

    // ---- stage 2: vertical 5-tap, half2 granularity (2048 units / 256 thr) -----
    #pragma unroll
    for (int k = 0; k < 8; k++) {
        int e2 = tid + k*256;
        int r  = e2 >> 9;                       // 0..3
        int ch = (e2 >> 6) & 7;
        int w2 = (e2 & 63) << 1;
        float2 a0 = __half22float2(*(const __half2*)(&sm_m[r  ][ch][w2]));
        float2 a1 = __half22float2(*(const __half2*)(&sm_m[r+1][ch][w2]));
        float2 a2 = __half22float2(*(const __half2*)(&sm_m[r+2][ch][w2]));
        float2 a3 = __half22float2(*(const __half2*)(&sm_m[r+3][ch][w2]));
        float2 a4 = __half22float2(*(const __half2*)(&sm_m[r+4][ch][w2]));
        float2 o;
        o.x = KW0*a0.x + KW1*a1.x + KW2*a2.x + KW1*a3.x + KW0*a4.x;
        o.y = KW0*a0.y + KW1*a1.y + KW2*a2.y + KW1*a3.y + KW0*a4.y;
        *(float2*)(&sm_t[r][ch][w2]) = o;
    }
    __syncthreads();

    // ---- stage 3: horizontal 5-tap, factor update, contraction (2 px/thread) ---
    const int row = tid >> 6;                   // 0..3
    const int w0  = (tid & 63) << 1;            // 0,2,..,126
    const int h   = h0 + row;
    const size_t pixoff = (size_t)h*WW + w0;
    const size_t hbase  = (size_t)b*NS*NS*HWP + pixoff;

    float un[NS][2];
    #pragma unroll
    for (int u = 0; u < NS; u++) {
        float tm2 = sm_t[row][u][(w0 + 126) & 127];
        float tm1 = sm_t[row][u][(w0 + 127) & 127];
        float t0  = sm_t[row][u][w0];
        float t1  = sm_t[row][u][w0 + 1];
        float tp2 = sm_t[row][u][(w0 + 2) & 127];
        float tp3 = sm_t[row][u][(w0 + 3) & 127];
        float s0 = KW0*tm2 + KW1*tm1 + KW2*t0 + KW1*t1 + KW0*tp2;
        float s1 = KW0*tm1 + KW1*t0  + KW2*t1 + KW1*tp2 + KW0*tp3;

        size_t off = ((size_t)(b*NS + u))*HWP + pixoff;
        float2 f = __half22float2(*(const __half2*)(upd + off));
        un[u][0] = __fdividef(f.x, s0 + EPSV);
        un[u][1] = __fdividef(f.y, s1 + EPSV);
        *(__half2*)(upd + off) = __floats2half2_rn(un[u][0], un[u][1]);
    }

    #pragma unroll
    for (int vh = 0; vh < 2; vh++) {
        float acc[4][2];
        #pragma unroll
        for (int v = 0; v < 4; v++) acc[v][0] = acc[v][1] = 0.f;

        #pragma unroll
        for (int u = 0; u < NS; u++) {
            #pragma unroll
            for (int v = 0; v < 4; v++) {
                int vv = vh*4 + v;
                int cc = (MODE == 0) ? (u*NS + vv) : (vv*NS + u);
                float2 f = __half22float2(*(const __half2*)(g_H0 + hbase + (size_t)cc*HWP));
                acc[v][0] += f.x * un[u][0];
                acc[v][1] += f.y * un[u][1];
            }
        }

        #pragma unroll
        for (int v = 0; v < 4; v++) {
            int vv = vh*4 + v;
            size_t off = ((size_t)(b*NS + vv))*HWP + pixoff;
            float2 o = __half22float2(*(const __half2*)(oth + off));
            *(__half2*)(mout + off) = __floats2half2_rn(acc[v][0]*o.x, acc[v][1]*o.y);
        }
    }
}

// ================= per-chain final: out = exp(log)*r_i*c_j + eps ===============
__global__ void k_final_c(const float* __restrict__ lg, float* __restrict__ out, int b0) {
    int t   = blockIdx.x*blockDim.x + threadIdx.x;   // 32768 threads (8 batches)
    int b   = b0 + (t >> 12);
    int pix = (t & 4095) << 2;

    float cf[NS][4];
    #pragma unroll
    for (int j = 0; j < NS; j++) {
        uint2 cv = *(const uint2*)(g_c + ((size_t)(b*NS + j))*HWP + pix);
        float2 c01 = __half22float2(*(__half2*)&cv.x);
        float2 c23 = __half22float2(*(__half2*)&cv.y);
        cf[j][0] = c01.x; cf[j][1] = c01.y; cf[j][2] = c23.x; cf[j][3] = c23.y;
    }
    #pragma unroll
    for (int i = 0; i < NS; i++) {
        uint2 rw = *(const uint2*)(g_r + ((size_t)(b*NS + i))*HWP + pix);
        float2 r01 = __half22float2(*(__half2*)&rw.x);
        float2 r23 = __half22float2(*(__half2*)&rw.y);
        #pragma unroll
        for (int j = 0; j < NS; j++) {
            size_t off = ((size_t)(b*NS*NS + i*NS + j))*HWP + pix;
            float4 v = *(const float4*)(lg + off);
            float4 o;
            o.x = expf(v.x)*r01.x*cf[j][0] + EPSV;
            o.y = expf(v.y)*r01.y*cf[j][1] + EPSV;
            o.z = expf(v.z)*r23.x*cf[j][2] + EPSV;
            o.w = expf(v.w)*r23.y*cf[j][3] + EPSV;
            *(float4*)(out + off) = o;
        }
    }
}

// ================= launch: 4 fully-independent chains, forked streams ===========
extern "C" void kernel_launch(void* const* d_in, const int* in_sizes, int n_in,
                              void* d_out, int out_size) {
    (void)in_sizes; (void)n_in; (void)out_size;
    const float* lg  = (const float*)d_in[0];
    float*       out = (float*)d_out;

    // one-time resources (created on first, non-capturing correctness call)
    static cudaStream_t cs[CHAINS] = {nullptr, nullptr, nullptr, nullptr};
    static cudaEvent_t  evFork = nullptr;
    static cudaEvent_t  evDone[CHAINS] = {nullptr, nullptr, nullptr, nullptr};
    if (evFork == nullptr) {
        cudaEventCreateWithFlags(&evFork, cudaEventDisableTiming);
        for (int k = 1; k < CHAINS; k++)
            cudaStreamCreateWithFlags(&cs[k], cudaStreamNonBlocking);
        for (int k = 1; k < CHAINS; k++)
            cudaEventCreateWithFlags(&evDone[k], cudaEventDisableTiming);
    }

    cudaEventRecord(evFork, 0);
    for (int k = 1; k < CHAINS; k++)
        cudaStreamWaitEvent(cs[k], evFork, 0);

    dim3 hg(HH/TH, CBAT);            // (32, 8) = 256 blocks per chain launch
    for (int k = 0; k < CHAINS; k++) {
        cudaStream_t s = (k == 0) ? (cudaStream_t)0 : cs[k];
        int b0 = k * CBAT;
        k_init_c<<<128, 256, 0, s>>>(lg, b0);
        for (int it = 0; it < 20; it++) {
            k_half<0><<<hg, 256, 0, s>>>(0, b0);   // row step: update r
            k_half<1><<<hg, 256, 0, s>>>(1, b0);   // col step: update c
        }
        k_final_c<<<128, 256, 0, s>>>(lg, out, b0);
        if (k > 0) cudaEventRecord(evDone[k], s);
    }
    for (int k = 1; k < CHAINS; k++)
        cudaStreamWaitEvent(0, evDone[k], 0);
}